// round 9
// baseline (speedup 1.0000x reference)
#include <cuda_runtime.h>
#include <cuda_bf16.h>
#include <float.h>
#include <math.h>

// Problem shape (fixed by reference setup_inputs)
#define B_   16
#define C_   256
#define H_   128
#define W_   128
#define HW_  (H_ * W_)           // 16384
#define HW4_ (HW_ / 4)           // 4096 float4 columns per image

#define N_PROD 4096              // producer blocks (R6 config)
#define TILE_H 4
#define N_CONS (B_ * (H_ / TILE_H))   // 512 consumer blocks

// Scratch: feat [B, 2, H, W]  (avg then max)
__device__ float g_feat[B_ * 2 * HW_];
// Per-row produced counter (0..2) and consumed counter. Zero at load;
// consumed-count protocol resets both each launch -> graph-replay clean.
__device__ int g_prod[B_ * H_];
__device__ int g_done[B_ * H_];

// ---------------------------------------------------------------------------
// Single fused grid: bids [0, 4096) = pure streaming producers (R6 shape),
// bids [4096, 4608) = conv consumers that land during the producer drain.
// ---------------------------------------------------------------------------
__global__ __launch_bounds__(256) void fused_kernel(
    const float* __restrict__ x,
    const float* __restrict__ conv_w,   // [1,2,3,3] OIHW
    float* __restrict__ out)            // [B,1,H,W]
{
    const int tid = threadIdx.x;
    const int bid = blockIdx.x;

    if (bid < N_PROD) {
        // ---------------- Producer: half-row channel mean+max ------------
        __shared__ float4 s_sum[256];
        __shared__ float4 s_max[256];

        const int col    = tid & 15;           // float4 column within half-row
        const int cs     = tid >> 4;           // channel split 0..15
        const int row_id = bid >> 1;           // 0..2047 == b*128 + h
        const int half   = bid & 1;
        const int b      = row_id >> 7;
        const int h      = row_id & 127;
        const int hw4    = (h << 5) + (half << 4) + col;

        const float4* xb = reinterpret_cast<const float4*>(x)
                         + (size_t)b * C_ * HW4_ + (size_t)(cs * 16) * HW4_ + hw4;

        float4 s = make_float4(0.f, 0.f, 0.f, 0.f);
        float4 m = make_float4(-FLT_MAX, -FLT_MAX, -FLT_MAX, -FLT_MAX);

        #pragma unroll
        for (int c = 0; c < 16; ++c) {
            float4 v = __ldcs(xb + (size_t)c * HW4_);
            s.x += v.x; s.y += v.y; s.z += v.z; s.w += v.w;
            m.x = fmaxf(m.x, v.x); m.y = fmaxf(m.y, v.y);
            m.z = fmaxf(m.z, v.z); m.w = fmaxf(m.w, v.w);
        }

        s_sum[tid] = s;
        s_max[tid] = m;
        __syncthreads();

        if (tid < 16) {
            #pragma unroll
            for (int k = 1; k < 16; ++k) {
                float4 ps = s_sum[tid + k * 16];
                float4 pm = s_max[tid + k * 16];
                s.x += ps.x; s.y += ps.y; s.z += ps.z; s.w += ps.w;
                m.x = fmaxf(m.x, pm.x); m.y = fmaxf(m.y, pm.y);
                m.z = fmaxf(m.z, pm.z); m.w = fmaxf(m.w, pm.w);
            }
            const float inv = 1.0f / (float)C_;
            float4 a = make_float4(s.x * inv, s.y * inv, s.z * inv, s.w * inv);

            float4* fa = reinterpret_cast<float4*>(g_feat)
                       + (size_t)b * 2 * HW4_ + hw4;
            fa[0]    = a;   // channel 0: avg
            fa[HW4_] = m;   // channel 1: max
            __threadfence();
        }
        __syncthreads();
        if (tid == 0) atomicAdd(&g_prod[row_id], 1);   // row ready at 2

    } else {
        // ---------------- Consumer: smem-tiled 3x3 conv + sigmoid --------
        __shared__ float s_f[2][TILE_H + 2][W_];
        __shared__ float s_w[18];

        const int cid = bid - N_PROD;        // 0..511
        const int b   = cid >> 5;            // 32 tiles per image
        const int h0  = (cid & 31) * TILE_H;

        if (tid < 18) s_w[tid] = __ldg(conv_w + tid);

        // Wait for the 4-6 producer rows this tile's halo needs.
        if (tid == 0) {
            for (int r = h0 - 1; r <= h0 + TILE_H; ++r) {
                if (r < 0 || r >= H_) continue;
                while (atomicAdd(&g_prod[b * H_ + r], 0) < 2) __nanosleep(128);
            }
            __threadfence();
        }
        __syncthreads();

        const float* fb = g_feat + (size_t)b * 2 * HW_;

        // Cooperative halo load: rows h0-1 .. h0+TILE_H, both channels.
        #pragma unroll
        for (int i = 0; i < 6; ++i) {
            const int idx = tid + i * 256;   // 0..1535
            const int ch  = idx / ((TILE_H + 2) * W_);
            const int rem = idx - ch * (TILE_H + 2) * W_;
            const int r   = rem >> 7;        // 0..5
            const int w   = rem & 127;
            const int hh  = h0 - 1 + r;
            float v = 0.f;
            if (hh >= 0 && hh < H_) v = fb[ch * HW_ + hh * W_ + w];
            s_f[ch][r][w] = v;
        }
        __syncthreads();

        // Bookkeeping: reads of g_feat are complete; last consumer of each
        // row resets its counters for the next graph replay.
        if (tid == 0) {
            for (int r = h0 - 1; r <= h0 + TILE_H; ++r) {
                if (r < 0 || r >= H_) continue;
                const int rr = r & 3;
                const int target =
                    ((rr == 0 && r != 0) || (rr == 3 && r != H_ - 1)) ? 2 : 1;
                const int g = b * H_ + r;
                if (atomicAdd(&g_done[g], 1) == target - 1) {
                    atomicExch(&g_done[g], 0);
                    atomicExch(&g_prod[g], 0);
                }
            }
        }

        // Each thread computes 2 pixels of the 4x128 tile.
        #pragma unroll
        for (int k = 0; k < 2; ++k) {
            const int p = tid + k * 256;     // 0..511
            const int r = p >> 7;            // local row 0..3
            const int w = p & 127;

            float acc = 0.f;
            #pragma unroll
            for (int kh = 0; kh < 3; ++kh) {
                #pragma unroll
                for (int kw = 0; kw < 3; ++kw) {
                    const int ww = w + kw - 1;
                    if (ww < 0 || ww >= W_) continue;
                    acc = fmaf(s_f[0][r + kh][ww], s_w[kh * 3 + kw],     acc);
                    acc = fmaf(s_f[1][r + kh][ww], s_w[9 + kh * 3 + kw], acc);
                }
            }
            out[(size_t)b * HW_ + (h0 + r) * W_ + w] =
                1.0f / (1.0f + __expf(-acc));
        }
    }
}

// ---------------------------------------------------------------------------
extern "C" void kernel_launch(void* const* d_in, const int* in_sizes, int n_in,
                              void* d_out, int out_size)
{
    const float* x      = (const float*)d_in[0];   // [16,256,128,128] f32
    const float* conv_w = (const float*)d_in[1];   // [1,2,3,3] f32
    float*       out    = (float*)d_out;           // [16,1,128,128] f32

    fused_kernel<<<N_PROD + N_CONS, 256>>>(x, conv_w, out);
}

// round 10
// speedup vs baseline: 1.0244x; 1.0244x over previous
#include <cuda_runtime.h>
#include <cuda_bf16.h>
#include <float.h>
#include <math.h>

// Problem shape (fixed by reference setup_inputs)
#define B_   16
#define C_   256
#define H_   128
#define W_   128
#define HW_  (H_ * W_)           // 16384
#define HW4_ (HW_ / 4)           // 4096 float4 columns per image

// Scratch: feat [B, 2, H, W]  (avg then max)
__device__ float g_feat[B_ * 2 * HW_];

// ---------------------------------------------------------------------------
// Kernel 1: channel-wise mean + max over C=256.  (R6 config, unroll 4)
// Block = half a spatial row: (16 float4 cols) x (16 channel-splits of 16 ch).
// 4096 blocks x 256 threads. unroll 4 limits front-batched LDG (MLP_p1=4) to
// suppress cross-CTA L1tex-queue spread on the last wave while keeping 32KB/SM
// of outstanding loads (>2x the latency-BW product).
// ---------------------------------------------------------------------------
__global__ __launch_bounds__(256) void reduce_mean_max_kernel(
    const float* __restrict__ x)
{
    cudaTriggerProgrammaticLaunchCompletion();

    __shared__ float4 s_sum[256];
    __shared__ float4 s_max[256];

    const int tid  = threadIdx.x;
    const int col  = tid & 15;                 // float4 column within half-row
    const int cs   = tid >> 4;                 // channel split 0..15

    const int blk    = blockIdx.x;             // 0..4095
    const int row_id = blk >> 1;               // 0..2047 == b*128 + h
    const int half   = blk & 1;
    const int b      = row_id >> 7;
    const int h      = row_id & 127;
    const int hw4    = (h << 5) + (half << 4) + col;

    const float4* xb = reinterpret_cast<const float4*>(x)
                     + (size_t)b * C_ * HW4_ + (size_t)(cs * 16) * HW4_ + hw4;

    float4 s = make_float4(0.f, 0.f, 0.f, 0.f);
    float4 m = make_float4(-FLT_MAX, -FLT_MAX, -FLT_MAX, -FLT_MAX);

    #pragma unroll 4
    for (int c = 0; c < 16; ++c) {
        float4 v = __ldcs(xb + (size_t)c * HW4_);
        s.x += v.x; s.y += v.y; s.z += v.z; s.w += v.w;
        m.x = fmaxf(m.x, v.x); m.y = fmaxf(m.y, v.y);
        m.z = fmaxf(m.z, v.z); m.w = fmaxf(m.w, v.w);
    }

    s_sum[tid] = s;
    s_max[tid] = m;
    __syncthreads();

    if (tid < 16) {
        #pragma unroll
        for (int k = 1; k < 16; ++k) {
            float4 ps = s_sum[tid + k * 16];
            float4 pm = s_max[tid + k * 16];
            s.x += ps.x; s.y += ps.y; s.z += ps.z; s.w += ps.w;
            m.x = fmaxf(m.x, pm.x); m.y = fmaxf(m.y, pm.y);
            m.z = fmaxf(m.z, pm.z); m.w = fmaxf(m.w, pm.w);
        }
        const float inv = 1.0f / (float)C_;
        float4 a = make_float4(s.x * inv, s.y * inv, s.z * inv, s.w * inv);

        float4* fa = reinterpret_cast<float4*>(g_feat)
                   + (size_t)b * 2 * HW4_ + hw4;
        fa[0]    = a;   // channel 0: avg
        fa[HW4_] = m;   // channel 1: max
    }
}

// ---------------------------------------------------------------------------
// Kernel 2: 3x3 conv (2 in ch, 1 out ch, pad 1, no bias) + sigmoid.
// One thread per output pixel (fastest measured config). PDL: weights load in
// the prologue, grid dependency sync, then conv against L2-hot g_feat.
// ---------------------------------------------------------------------------
__global__ __launch_bounds__(256) void conv_sigmoid_kernel(
    const float* __restrict__ conv_w,   // [1,2,3,3] OIHW
    float* __restrict__ out)            // [B,1,H,W]
{
    const int idx = blockIdx.x * blockDim.x + threadIdx.x;  // 0 .. B*HW-1
    const int b  = idx >> 14;           // / HW_
    const int hw = idx & (HW_ - 1);
    const int h  = hw >> 7;             // / W_
    const int w  = hw & (W_ - 1);

    // Prologue (overlaps producer drain): weights into registers.
    float wk[18];
    #pragma unroll
    for (int i = 0; i < 18; ++i) wk[i] = __ldg(conv_w + i);

    cudaGridDependencySynchronize();

    const float* f0 = g_feat + (size_t)b * 2 * HW_;   // avg channel
    const float* f1 = f0 + HW_;                       // max channel

    float acc = 0.f;
    #pragma unroll
    for (int kh = 0; kh < 3; ++kh) {
        const int hh = h + kh - 1;
        if (hh < 0 || hh >= H_) continue;
        #pragma unroll
        for (int kw = 0; kw < 3; ++kw) {
            const int ww = w + kw - 1;
            if (ww < 0 || ww >= W_) continue;
            const int off = hh * W_ + ww;
            acc = fmaf(f0[off], wk[kh * 3 + kw], acc);
            acc = fmaf(f1[off], wk[9 + kh * 3 + kw], acc);
        }
    }

    out[idx] = 1.0f / (1.0f + __expf(-acc));
}

// ---------------------------------------------------------------------------
extern "C" void kernel_launch(void* const* d_in, const int* in_sizes, int n_in,
                              void* d_out, int out_size)
{
    const float* x      = (const float*)d_in[0];   // [16,256,128,128] f32
    const float* conv_w = (const float*)d_in[1];   // [1,2,3,3] f32
    float*       out    = (float*)d_out;           // [16,1,128,128] f32

    // Kernel 1: 4096 blocks x 256 threads
    reduce_mean_max_kernel<<<4096, 256>>>(x);

    // Kernel 2: 1024 blocks x 256 threads, PDL-overlapped launch
    cudaLaunchConfig_t cfg = {};
    cfg.gridDim  = dim3((B_ * HW_) / 256, 1, 1);
    cfg.blockDim = dim3(256, 1, 1);
    cfg.dynamicSmemBytes = 0;
    cfg.stream = 0;

    cudaLaunchAttribute attrs[1];
    attrs[0].id = cudaLaunchAttributeProgrammaticStreamSerialization;
    attrs[0].val.programmaticStreamSerializationAllowed = 1;
    cfg.attrs = attrs;
    cfg.numAttrs = 1;

    cudaLaunchKernelEx(&cfg, conv_sigmoid_kernel, conv_w, out);
}